// round 4
// baseline (speedup 1.0000x reference)
#include <cuda_runtime.h>
#include <stdint.h>

#define NTOT  (8*32*32*9)   // 73728
#define KSEL  512
#define HF_   32
#define WF_   32
#define CCH   1024
#define FEAT  256
#define OUTC  84
#define SS_   14
#define NSAMP 196
#define DET_THRC 0.7f
#define NMS_IOUC 0.7f
#define NBINS 4096

typedef unsigned long long ull;

// ---------------- device scratch (static globals; zero-initialized) ---------
__device__ uint64_t g_cand[NTOT];
__device__ int      g_cand_count;                 // reset by k_select
__device__ __align__(16) int g_hist[NBINS];       // reset by k_select
__device__ int      g_valid[KSEL];
__device__ int      g_assign[KSEL];
__device__ float    g_rois[KSEL*4];
__device__ float    g_shifted[KSEL*4];
__device__ unsigned g_sup[KSEL*16];
__device__ unsigned g_supany[16];                 // reset by resolver
__device__ int      g_keep[KSEL];
__device__ int      g_done;                       // reset by resolver

// ---------------- filter: score > 0.7 -> key + 4096-bin histogram -----------
__global__ void k_filter(const float* __restrict__ pred) {
    int i = blockIdx.x * blockDim.x + threadIdx.x;
    float s = (i < NTOT) ? pred[i] : 0.0f;
    bool c = (s > DET_THRC);
    unsigned m = __ballot_sync(0xffffffffu, c);
    int n = __popc(m);
    int base = 0;
    if ((threadIdx.x & 31) == 0 && n)
        base = atomicAdd(&g_cand_count, n);
    base = __shfl_sync(0xffffffffu, base, 0);
    if (c) {
        int r = __popc(m & ((1u << (threadIdx.x & 31)) - 1u));
        unsigned u = __float_as_uint(s); // s > 0 -> monotone as unsigned
        g_cand[base + r] = ((uint64_t)u << 32) | (unsigned)(0xFFFFFFFFu - (unsigned)i);
        atomicAdd(&g_hist[u >> 19], 1);
    }
}

// ------- single-block: histogram cutoff + 1-pass collect + hybrid bitonic ---
__global__ void __launch_bounds__(1024) k_select(const float* __restrict__ rois,
                                                 const float* __restrict__ anchors,
                                                 const int*   __restrict__ assign) {
    __shared__ int      sh_hist[NBINS];
    __shared__ int      sh_chunk[1024];
    __shared__ int      sh_warp[32];
    __shared__ unsigned sh_T;
    __shared__ int      sh_cnt;
    __shared__ uint64_t sh_keys[1024];
    int tid = threadIdx.x;
    int lane = tid & 31, wid = tid >> 5;

    int M = g_cand_count; if (M > NTOT) M = NTOT;
    __syncthreads();
    if (tid == 0) { g_cand_count = 0; sh_cnt = 0; }

    int4 h = ((const int4*)g_hist)[tid];
    ((int4*)g_hist)[tid] = make_int4(0, 0, 0, 0);
    sh_hist[tid*4+0] = h.x; sh_hist[tid*4+1] = h.y;
    sh_hist[tid*4+2] = h.z; sh_hist[tid*4+3] = h.w;
    int csum = h.x + h.y + h.z + h.w;
    sh_chunk[tid] = csum;
    int ws = csum;
    #pragma unroll
    for (int off = 16; off > 0; off >>= 1) ws += __shfl_down_sync(0xffffffffu, ws, off);
    if (lane == 0) sh_warp[wid] = ws;
    __syncthreads();

    if (tid == 0) {
        unsigned T = 1u;
        int cum = 0; int w;
        bool found = false;
        for (w = 31; w >= 0; w--) {
            if (cum + sh_warp[w] >= KSEL) { found = true; break; }
            cum += sh_warp[w];
        }
        if (found) {
            int c;
            for (c = 31; c >= 0; c--) {
                int t = sh_chunk[w*32 + c];
                if (cum + t >= KSEL) break;
                cum += t;
            }
            int base = (w*32 + c) * 4;
            int b;
            for (b = 3; b >= 0; b--) {
                int t = sh_hist[base + b];
                if (cum + t >= KSEL) break;
                cum += t;
            }
            T = (unsigned)(base + b) << 19;
        }
        sh_T = T;
    }
    __syncthreads();
    unsigned T = sh_T;

    for (int j = tid; j < M; j += 1024) {
        uint64_t k = g_cand[j];
        if ((unsigned)(k >> 32) >= T) {
            int p = atomicAdd(&sh_cnt, 1);
            if (p < 1024) sh_keys[p] = k;
        }
    }
    __syncthreads();
    int cnt = sh_cnt; if (cnt > 1024) cnt = 1024;
    if (tid >= cnt) sh_keys[tid] = 0ull;
    __syncthreads();

    // hybrid bitonic sort (descending)
    uint64_t v = sh_keys[tid];
    #pragma unroll
    for (int size = 2; size <= 32; size <<= 1) {
        #pragma unroll
        for (int stride = size >> 1; stride >= 1; stride >>= 1) {
            uint64_t o = __shfl_xor_sync(0xffffffffu, v, stride);
            bool lower = (tid & stride) == 0;
            bool desc  = (tid & size) == 0;
            uint64_t mx = v > o ? v : o, mn = v > o ? o : v;
            v = (desc == lower) ? mx : mn;
        }
    }
    sh_keys[tid] = v;
    __syncthreads();
    for (int size = 64; size <= 1024; size <<= 1) {
        for (int stride = size >> 1; stride >= 32; stride >>= 1) {
            int j = tid ^ stride;
            if (j > tid) {
                uint64_t a = sh_keys[tid], b = sh_keys[j];
                bool desc = (tid & size) == 0;
                if (desc ? (a < b) : (a > b)) { sh_keys[tid] = b; sh_keys[j] = a; }
            }
            __syncthreads();
        }
        v = sh_keys[tid];
        #pragma unroll
        for (int stride = 16; stride >= 1; stride >>= 1) {
            uint64_t o = __shfl_xor_sync(0xffffffffu, v, stride);
            bool lower = (tid & stride) == 0;
            bool desc  = (tid & size) == 0;
            uint64_t mx = v > o ? v : o, mn = v > o ? o : v;
            v = (desc == lower) ? mx : mn;
        }
        sh_keys[tid] = v;
        __syncthreads();
    }

    if (tid < KSEL) {
        uint64_t k = sh_keys[tid];
        unsigned u = (unsigned)(k >> 32);
        int idx = 0, vv = 0;
        if (u != 0u) { idx = (int)(0xFFFFFFFFu - (unsigned)(k & 0xFFFFFFFFu)); vv = 1; }
        g_valid[tid] = vv;
        int a = assign[idx];
        g_assign[tid] = a;
        float fa = (float)a * 1024.0f;
        #pragma unroll
        for (int c = 0; c < 4; c++) g_rois[tid*4 + c] = rois[idx*4 + c];
        float cy = anchors[idx*4+0], cx = anchors[idx*4+1];
        float hh = anchors[idx*4+2], ww = anchors[idx*4+3];
        g_shifted[tid*4+0] = cy - hh*0.5f + fa;
        g_shifted[tid*4+1] = cx - ww*0.5f + fa;
        g_shifted[tid*4+2] = cy + hh*0.5f + fa;
        g_shifted[tid*4+3] = cx + ww*0.5f + fa;
    }
}

// ------- NMS sup masks (16 blocks x 512 thr) + last-block greedy resolve ----
__global__ void __launch_bounds__(512) k_supres() {
    __shared__ float4 sb[KSEL];
    __shared__ int    s_last;
    int tid = threadIdx.x;
    const float4* gs = (const float4*)g_shifted;
    sb[tid] = gs[tid];
    __syncthreads();

    int i = blockIdx.x * 32 + (tid >> 4);
    int w = tid & 15;
    float4 bi = sb[i];
    float ai = (bi.z - bi.x) * (bi.w - bi.y);
    unsigned bits = 0u;
    #pragma unroll 8
    for (int b = 0; b < 32; b++) {
        int j = w*32 + b;
        if (j > i) {
            float4 bj = sb[j];
            float yA = fmaxf(bi.x, bj.x), xA = fmaxf(bi.y, bj.y);
            float yB = fminf(bi.z, bj.z), xB = fminf(bi.w, bj.w);
            float inter = fmaxf(yB - yA, 0.0f) * fmaxf(xB - xA, 0.0f);
            float aj = (bj.z - bj.x) * (bj.w - bj.y);
            if (inter > NMS_IOUC * (ai + aj - inter + 1e-8f)) bits |= (1u << b);
        }
    }
    g_sup[i*16 + w] = bits;
    if (bits) atomicOr(&g_supany[i >> 5], 1u << (i & 31));

    // grid-arrival: last block to finish performs the sequential resolve
    __threadfence();
    __syncthreads();
    if (tid == 0) s_last = (atomicAdd(&g_done, 1) == 15) ? 1 : 0;
    __syncthreads();
    if (!s_last) return;

    __shared__ unsigned ssup[KSEL*16];
    __shared__ unsigned sany[16];
    __shared__ unsigned sword[16];
    __threadfence();
    #pragma unroll
    for (int k2 = tid; k2 < KSEL*16; k2 += 512) ssup[k2] = g_sup[k2];
    int v = g_valid[tid];
    unsigned bm = __ballot_sync(0xffffffffu, v != 0);
    if ((tid & 31) == 0) sword[tid >> 5] = bm;
    if (tid < 16) { sany[tid] = g_supany[tid]; g_supany[tid] = 0u; }
    if (tid == 0) g_done = 0;
    __syncthreads();

    if (tid < 32) {
        int lane = tid;
        unsigned word = (lane < 16) ? sword[lane] : 0u;
        for (int ww = 0; ww < 16; ww++) {
            unsigned anyw = sany[ww];
            if (!anyw) continue;
            for (int b = 0; b < 32; b++) {
                if (!((anyw >> b) & 1u)) continue;
                int ii = ww*32 + b;
                unsigned wi = __shfl_sync(0xffffffffu, word, ww);
                if ((wi >> b) & 1u) {
                    if (lane < 16) word &= ~ssup[ii*16 + lane];
                }
            }
        }
        if (lane < 16) sword[lane] = word;
    }
    __syncthreads();
    g_keep[tid] = (int)((sword[tid >> 5] >> (tid & 31)) & 1u);
}

// ------- fused head: roi-align + GEMM1 + BN/ReLU + GEMM2 + masked out -------
// 128 blocks x 256 threads, 4 rois per block
__global__ void __launch_bounds__(256) k_head(const float* __restrict__ feats,
                                              const float* __restrict__ W1,
                                              const float* __restrict__ b1,
                                              const float* __restrict__ gamma,
                                              const float* __restrict__ beta,
                                              const float* __restrict__ mm,
                                              const float* __restrict__ mv,
                                              const float* __restrict__ W2,
                                              const float* __restrict__ b2,
                                              float* __restrict__ out) {
    __shared__ __align__(16) float sp[CCH*4];   // pooled [c][r]  16KB
    __shared__ float sh[4*FEAT];                // hdd [r][c]      4KB
    __shared__ float wmap[1024];
    __shared__ int   plist[4][96];
    __shared__ float wlist[4][96];
    __shared__ int   cnt[4];
    __shared__ float srois[16];
    __shared__ int   sassign[4];

    int r0  = blockIdx.x * 4;
    int tid = threadIdx.x;
    if (tid < 16) srois[tid] = g_rois[r0*4 + tid];
    if (tid < 4)  { cnt[tid] = 0; sassign[tid] = g_assign[r0 + tid]; }
    __syncthreads();

    // build per-roi pixel weight lists
    for (int rr = 0; rr < 4; rr++) {
        for (int i = tid; i < 1024; i += 256) wmap[i] = 0.0f;
        __syncthreads();
        if (tid < NSAMP) {
            const float sc = 32.0f / 1024.0f;
            float ry1 = srois[rr*4+0] * sc, rx1 = srois[rr*4+1] * sc;
            float ry2 = srois[rr*4+2] * sc, rx2 = srois[rr*4+3] * sc;
            int sy = tid / SS_, sx = tid % SS_;
            float fy = ((float)sy + 0.5f) / (float)SS_;
            float fx = ((float)sx + 0.5f) / (float)SS_;
            float yy = ry1 + fy * (ry2 - ry1) - 0.5f;
            float xx = rx1 + fx * (rx2 - rx1) - 0.5f;
            float yc = fminf(fmaxf(yy, 0.0f), 31.0f);
            float xc = fminf(fmaxf(xx, 0.0f), 31.0f);
            float y0 = floorf(yc), x0 = floorf(xc);
            float wy = yc - y0,  wx = xc - x0;
            int y0i = (int)y0, x0i = (int)x0;
            int y1i = min(y0i + 1, 31), x1i = min(x0i + 1, 31);
            atomicAdd(&wmap[y0i*32 + x0i], (1.0f - wy) * (1.0f - wx));
            atomicAdd(&wmap[y0i*32 + x1i], (1.0f - wy) * wx);
            atomicAdd(&wmap[y1i*32 + x0i], wy * (1.0f - wx));
            atomicAdd(&wmap[y1i*32 + x1i], wy * wx);
        }
        __syncthreads();
        for (int p = tid; p < 1024; p += 256) {
            float w = wmap[p];
            if (w != 0.0f) {
                int pos = atomicAdd(&cnt[rr], 1);
                plist[rr][pos] = p; wlist[rr][pos] = w;
            }
        }
        __syncthreads();
    }

    // gather: thread = channel quad [tid*4 .. tid*4+3]
    const float inv = 1.0f / 196.0f;
    for (int rr = 0; rr < 4; rr++) {
        const float4* fb = (const float4*)(feats + (size_t)sassign[rr] * (HF_*WF_*CCH));
        int n = cnt[rr];
        float ax = 0.f, ay = 0.f, az = 0.f, aw = 0.f;
        #pragma unroll 2
        for (int e = 0; e < n; e++) {
            int   p = plist[rr][e];
            float w = wlist[rr][e];
            float4 vv = fb[p * 256 + tid];
            ax += w * vv.x; ay += w * vv.y; az += w * vv.z; aw += w * vv.w;
        }
        int c4 = tid * 4;
        sp[(c4+0)*4 + rr] = ax * inv;
        sp[(c4+1)*4 + rr] = ay * inv;
        sp[(c4+2)*4 + rr] = az * inv;
        sp[(c4+3)*4 + rr] = aw * inv;
    }
    __syncthreads();

    // GEMM1 (f32x2): col = tid, 4 rois
    ull a01 = 0ull, a23 = 0ull;
    const ull* spu = (const ull*)sp;
    #pragma unroll 4
    for (int c = 0; c < 1024; c++) {
        float w = W1[c * 256 + tid];
        ull w2;
        asm("mov.b64 %0, {%1, %1};" : "=l"(w2) : "r"(__float_as_uint(w)));
        asm("fma.rn.f32x2 %0, %1, %2, %0;" : "+l"(a01) : "l"(spu[c*2+0]), "l"(w2));
        asm("fma.rn.f32x2 %0, %1, %2, %0;" : "+l"(a23) : "l"(spu[c*2+1]), "l"(w2));
    }
    float af[4];
    {
        unsigned lo, hi;
        asm("mov.b64 {%0, %1}, %2;" : "=r"(lo), "=r"(hi) : "l"(a01));
        af[0] = __uint_as_float(lo); af[1] = __uint_as_float(hi);
        asm("mov.b64 {%0, %1}, %2;" : "=r"(lo), "=r"(hi) : "l"(a23));
        af[2] = __uint_as_float(lo); af[3] = __uint_as_float(hi);
    }
    {
        float m  = mm[tid];
        float vr = rsqrtf(mv[tid] + 1e-3f);
        float ga = gamma[tid];
        float be = beta[tid];
        float bb = b1[tid];
        #pragma unroll
        for (int r = 0; r < 4; r++) {
            float hv = (af[r] + bb - m) * vr * ga + be;
            sh[r*FEAT + tid] = fmaxf(hv, 0.0f);
        }
    }
    __syncthreads();

    // GEMM2: 4 rois x 84 outs = 336 dot products over 256
    #pragma unroll
    for (int q = 0; q < 2; q++) {
        int j = q*256 + tid;
        if (j < 336) {
            int o = j >> 2, r = j & 3;
            int kg = r0 + r;
            float acc = b2[o];
            const float* hrow = &sh[r*FEAT];
            #pragma unroll 4
            for (int c = 0; c < 256; c++) acc += hrow[c] * W2[c*OUTC + o];
            float keepf = (float)g_keep[kg];
            if (o < 4) out[KSEL*80 + kg*4 + o] = (srois[r*4 + o] + acc) * keepf;
            else       out[(size_t)kg*80 + (o - 4)] = acc * keepf;
        } else if (j < 340) {
            int kg = r0 + (j - 336);
            out[KSEL*80 + KSEL*4 + kg] = (float)g_keep[kg];
        }
    }
}

// ---------------- launch ----------------------------------------------------
extern "C" void kernel_launch(void* const* d_in, const int* in_sizes, int n_in,
                              void* d_out, int out_size) {
    const float* pred    = (const float*)d_in[0];
    const float* rois    = (const float*)d_in[1];
    const float* anchors = (const float*)d_in[2];
    const int*   assign  = (const int*)  d_in[3];
    const float* feats   = (const float*)d_in[4];
    const float* W1      = (const float*)d_in[5];
    const float* b1      = (const float*)d_in[6];
    const float* gamma   = (const float*)d_in[7];
    const float* beta    = (const float*)d_in[8];
    const float* mm      = (const float*)d_in[9];
    const float* mv      = (const float*)d_in[10];
    const float* W2      = (const float*)d_in[11];
    const float* b2      = (const float*)d_in[12];
    float* out = (float*)d_out;

    k_filter<<<(NTOT + 255) / 256, 256>>>(pred);
    k_select<<<1, 1024>>>(rois, anchors, assign);
    k_supres<<<16, 512>>>();
    k_head<<<KSEL / 4, 256>>>(feats, W1, b1, gamma, beta, mm, mv, W2, b2, out);
}

// round 5
// speedup vs baseline: 1.6246x; 1.6246x over previous
#include <cuda_runtime.h>
#include <stdint.h>

#define NTOT  (8*32*32*9)   // 73728
#define KSEL  512
#define HF_   32
#define WF_   32
#define CCH   1024
#define FEAT  256
#define OUTC  84
#define SS_   14
#define NSAMP 196
#define DET_THRC 0.7f
#define NMS_IOUC 0.7f
#define NBINS 4096

typedef unsigned long long ull;

// ---------------- device scratch (static globals; zero-initialized) ---------
__device__ uint64_t g_cand[NTOT];
__device__ int      g_cand_count;                 // reset by k_select
__device__ __align__(16) int g_hist[NBINS];       // reset by k_select
__device__ int      g_valid[KSEL];
__device__ int      g_assign[KSEL];
__device__ float    g_rois[KSEL*4];
__device__ float    g_shifted[KSEL*4];
__device__ unsigned g_sup[KSEL*16];
__device__ unsigned g_supany[16];                 // reset by resolver
__device__ int      g_keep[KSEL];
__device__ int      g_done;                       // reset by resolver
__device__ __align__(16) float g_poolT[KSEL*CCH]; // [group=k/8][c][k%8]
__device__ __align__(16) float g_part[4*KSEL*FEAT]; // [kc][roi][col]

// ---------------- filter: score > 0.7 -> key + 4096-bin histogram -----------
__global__ void k_filter(const float* __restrict__ pred) {
    int i = blockIdx.x * blockDim.x + threadIdx.x;
    float s = (i < NTOT) ? pred[i] : 0.0f;
    bool c = (s > DET_THRC);
    unsigned m = __ballot_sync(0xffffffffu, c);
    int n = __popc(m);
    int base = 0;
    if ((threadIdx.x & 31) == 0 && n)
        base = atomicAdd(&g_cand_count, n);
    base = __shfl_sync(0xffffffffu, base, 0);
    if (c) {
        int r = __popc(m & ((1u << (threadIdx.x & 31)) - 1u));
        unsigned u = __float_as_uint(s); // s > 0 -> monotone as unsigned
        g_cand[base + r] = ((uint64_t)u << 32) | (unsigned)(0xFFFFFFFFu - (unsigned)i);
        atomicAdd(&g_hist[u >> 19], 1);
    }
}

// ------- single-block: histogram cutoff + 1-pass collect + hybrid bitonic ---
__global__ void __launch_bounds__(1024) k_select(const float* __restrict__ rois,
                                                 const float* __restrict__ anchors,
                                                 const int*   __restrict__ assign) {
    __shared__ int      sh_hist[NBINS];
    __shared__ int      sh_chunk[1024];
    __shared__ int      sh_warp[32];
    __shared__ unsigned sh_T;
    __shared__ int      sh_cnt;
    __shared__ uint64_t sh_keys[1024];
    int tid = threadIdx.x;
    int lane = tid & 31, wid = tid >> 5;

    int M = g_cand_count; if (M > NTOT) M = NTOT;
    __syncthreads();
    if (tid == 0) { g_cand_count = 0; sh_cnt = 0; }

    int4 h = ((const int4*)g_hist)[tid];
    ((int4*)g_hist)[tid] = make_int4(0, 0, 0, 0);
    sh_hist[tid*4+0] = h.x; sh_hist[tid*4+1] = h.y;
    sh_hist[tid*4+2] = h.z; sh_hist[tid*4+3] = h.w;
    int csum = h.x + h.y + h.z + h.w;
    sh_chunk[tid] = csum;
    int ws = csum;
    #pragma unroll
    for (int off = 16; off > 0; off >>= 1) ws += __shfl_down_sync(0xffffffffu, ws, off);
    if (lane == 0) sh_warp[wid] = ws;
    __syncthreads();

    if (tid == 0) {
        unsigned T = 1u;
        int cum = 0; int w;
        bool found = false;
        for (w = 31; w >= 0; w--) {
            if (cum + sh_warp[w] >= KSEL) { found = true; break; }
            cum += sh_warp[w];
        }
        if (found) {
            int c;
            for (c = 31; c >= 0; c--) {
                int t = sh_chunk[w*32 + c];
                if (cum + t >= KSEL) break;
                cum += t;
            }
            int base = (w*32 + c) * 4;
            int b;
            for (b = 3; b >= 0; b--) {
                int t = sh_hist[base + b];
                if (cum + t >= KSEL) break;
                cum += t;
            }
            T = (unsigned)(base + b) << 19;
        }
        sh_T = T;
    }
    __syncthreads();
    unsigned T = sh_T;

    for (int j = tid; j < M; j += 1024) {
        uint64_t k = g_cand[j];
        if ((unsigned)(k >> 32) >= T) {
            int p = atomicAdd(&sh_cnt, 1);
            if (p < 1024) sh_keys[p] = k;
        }
    }
    __syncthreads();
    int cnt = sh_cnt; if (cnt > 1024) cnt = 1024;
    if (tid >= cnt) sh_keys[tid] = 0ull;
    __syncthreads();

    // hybrid bitonic sort (descending)
    uint64_t v = sh_keys[tid];
    #pragma unroll
    for (int size = 2; size <= 32; size <<= 1) {
        #pragma unroll
        for (int stride = size >> 1; stride >= 1; stride >>= 1) {
            uint64_t o = __shfl_xor_sync(0xffffffffu, v, stride);
            bool lower = (tid & stride) == 0;
            bool desc  = (tid & size) == 0;
            uint64_t mx = v > o ? v : o, mn = v > o ? o : v;
            v = (desc == lower) ? mx : mn;
        }
    }
    sh_keys[tid] = v;
    __syncthreads();
    for (int size = 64; size <= 1024; size <<= 1) {
        for (int stride = size >> 1; stride >= 32; stride >>= 1) {
            int j = tid ^ stride;
            if (j > tid) {
                uint64_t a = sh_keys[tid], b = sh_keys[j];
                bool desc = (tid & size) == 0;
                if (desc ? (a < b) : (a > b)) { sh_keys[tid] = b; sh_keys[j] = a; }
            }
            __syncthreads();
        }
        v = sh_keys[tid];
        #pragma unroll
        for (int stride = 16; stride >= 1; stride >>= 1) {
            uint64_t o = __shfl_xor_sync(0xffffffffu, v, stride);
            bool lower = (tid & stride) == 0;
            bool desc  = (tid & size) == 0;
            uint64_t mx = v > o ? v : o, mn = v > o ? o : v;
            v = (desc == lower) ? mx : mn;
        }
        sh_keys[tid] = v;
        __syncthreads();
    }

    if (tid < KSEL) {
        uint64_t k = sh_keys[tid];
        unsigned u = (unsigned)(k >> 32);
        int idx = 0, vv = 0;
        if (u != 0u) { idx = (int)(0xFFFFFFFFu - (unsigned)(k & 0xFFFFFFFFu)); vv = 1; }
        g_valid[tid] = vv;
        int a = assign[idx];
        g_assign[tid] = a;
        float fa = (float)a * 1024.0f;
        #pragma unroll
        for (int c = 0; c < 4; c++) g_rois[tid*4 + c] = rois[idx*4 + c];
        float cy = anchors[idx*4+0], cx = anchors[idx*4+1];
        float hh = anchors[idx*4+2], ww = anchors[idx*4+3];
        g_shifted[tid*4+0] = cy - hh*0.5f + fa;
        g_shifted[tid*4+1] = cx - ww*0.5f + fa;
        g_shifted[tid*4+2] = cy + hh*0.5f + fa;
        g_shifted[tid*4+3] = cx + ww*0.5f + fa;
    }
}

// ------- NMS sup masks (16 blocks x 512 thr) + last-block greedy resolve ----
__global__ void __launch_bounds__(512) k_supres() {
    __shared__ float4 sb[KSEL];
    __shared__ int    s_last;
    int tid = threadIdx.x;
    const float4* gs = (const float4*)g_shifted;
    sb[tid] = gs[tid];
    __syncthreads();

    int i = blockIdx.x * 32 + (tid >> 4);
    int w = tid & 15;
    float4 bi = sb[i];
    float ai = (bi.z - bi.x) * (bi.w - bi.y);
    unsigned bits = 0u;
    #pragma unroll 8
    for (int b = 0; b < 32; b++) {
        int j = w*32 + b;
        if (j > i) {
            float4 bj = sb[j];
            float yA = fmaxf(bi.x, bj.x), xA = fmaxf(bi.y, bj.y);
            float yB = fminf(bi.z, bj.z), xB = fminf(bi.w, bj.w);
            float inter = fmaxf(yB - yA, 0.0f) * fmaxf(xB - xA, 0.0f);
            float aj = (bj.z - bj.x) * (bj.w - bj.y);
            if (inter > NMS_IOUC * (ai + aj - inter + 1e-8f)) bits |= (1u << b);
        }
    }
    g_sup[i*16 + w] = bits;
    if (bits) atomicOr(&g_supany[i >> 5], 1u << (i & 31));

    __threadfence();
    __syncthreads();
    if (tid == 0) s_last = (atomicAdd(&g_done, 1) == 15) ? 1 : 0;
    __syncthreads();
    if (!s_last) return;

    __shared__ unsigned ssup[KSEL*16];
    __shared__ unsigned sany[16];
    __shared__ unsigned sword[16];
    __threadfence();
    #pragma unroll
    for (int k2 = tid; k2 < KSEL*16; k2 += 512) ssup[k2] = g_sup[k2];
    int v = g_valid[tid];
    unsigned bm = __ballot_sync(0xffffffffu, v != 0);
    if ((tid & 31) == 0) sword[tid >> 5] = bm;
    if (tid < 16) { sany[tid] = g_supany[tid]; g_supany[tid] = 0u; }
    if (tid == 0) g_done = 0;
    __syncthreads();

    if (tid < 32) {
        int lane = tid;
        unsigned word = (lane < 16) ? sword[lane] : 0u;
        for (int ww = 0; ww < 16; ww++) {
            unsigned anyw = sany[ww];
            if (!anyw) continue;
            for (int b = 0; b < 32; b++) {
                if (!((anyw >> b) & 1u)) continue;
                int ii = ww*32 + b;
                unsigned wi = __shfl_sync(0xffffffffu, word, ww);
                if ((wi >> b) & 1u) {
                    if (lane < 16) word &= ~ssup[ii*16 + lane];
                }
            }
        }
        if (lane < 16) sword[lane] = word;
    }
    __syncthreads();
    g_keep[tid] = (int)((sword[tid >> 5] >> (tid & 31)) & 1u);
}

// ------- ROI align: 1 block/roi, float4 gather, writes transposed pooled ----
__global__ void __launch_bounds__(256) k_roialign(const float* __restrict__ feats) {
    __shared__ float wmap[1024];
    __shared__ int   plist[128];
    __shared__ float wlist[128];
    __shared__ int   cnt;
    int k   = blockIdx.x;
    int tid = threadIdx.x;
    for (int i = tid; i < 1024; i += 256) wmap[i] = 0.0f;
    if (tid == 0) cnt = 0;
    __syncthreads();

    const float sc = 32.0f / 1024.0f;
    float ry1 = g_rois[k*4+0] * sc, rx1 = g_rois[k*4+1] * sc;
    float ry2 = g_rois[k*4+2] * sc, rx2 = g_rois[k*4+3] * sc;

    if (tid < NSAMP) {
        int sy = tid / SS_, sx = tid % SS_;
        float fy = ((float)sy + 0.5f) / (float)SS_;
        float fx = ((float)sx + 0.5f) / (float)SS_;
        float yy = ry1 + fy * (ry2 - ry1) - 0.5f;
        float xx = rx1 + fx * (rx2 - rx1) - 0.5f;
        float yc = fminf(fmaxf(yy, 0.0f), 31.0f);
        float xc = fminf(fmaxf(xx, 0.0f), 31.0f);
        float y0 = floorf(yc), x0 = floorf(xc);
        float wy = yc - y0,  wx = xc - x0;
        int y0i = (int)y0, x0i = (int)x0;
        int y1i = min(y0i + 1, 31), x1i = min(x0i + 1, 31);
        atomicAdd(&wmap[y0i*32 + x0i], (1.0f - wy) * (1.0f - wx));
        atomicAdd(&wmap[y0i*32 + x1i], (1.0f - wy) * wx);
        atomicAdd(&wmap[y1i*32 + x0i], wy * (1.0f - wx));
        atomicAdd(&wmap[y1i*32 + x1i], wy * wx);
    }
    __syncthreads();

    for (int p = tid; p < 1024; p += 256) {
        float w = wmap[p];
        if (w != 0.0f) {
            int pos = atomicAdd(&cnt, 1);
            plist[pos] = p; wlist[pos] = w;
        }
    }
    __syncthreads();

    int n = cnt;
    const float4* fb = (const float4*)(feats + (size_t)g_assign[k] * (HF_*WF_*CCH));
    float ax = 0.f, ay = 0.f, az = 0.f, aw = 0.f;
    #pragma unroll 4
    for (int e = 0; e < n; e++) {
        int   p = plist[e];
        float w = wlist[e];
        float4 vv = fb[p * 256 + tid];
        ax += w * vv.x; ay += w * vv.y; az += w * vv.z; aw += w * vv.w;
    }
    const float inv = 1.0f / 196.0f;
    float* po = g_poolT + (size_t)(k >> 3) * 8192 + (k & 7);
    int c4 = tid * 4;
    po[(c4+0)*8] = ax * inv;
    po[(c4+1)*8] = ay * inv;
    po[(c4+2)*8] = az * inv;
    po[(c4+3)*8] = aw * inv;
}

// ------- GEMM1a: K-split partials. grid (64 groups, 4 K-chunks) x 256 thr ---
__global__ void __launch_bounds__(256) k_gemm1a(const float* __restrict__ W1) {
    __shared__ __align__(16) float sp[256*8];   // [c in chunk][8 rois]
    int g   = blockIdx.x;    // roi group (8 rois)
    int kc  = blockIdx.y;    // K chunk of 256
    int tid = threadIdx.x;   // output col

    const float4* src = (const float4*)(g_poolT + (size_t)g * 8192 + kc * 2048);
    float4* dst = (float4*)sp;
    #pragma unroll
    for (int i = tid; i < 512; i += 256) dst[i] = src[i];
    __syncthreads();

    const float* w1 = W1 + (size_t)(kc * 256) * 256 + tid;
    ull a0 = 0ull, a1 = 0ull, a2 = 0ull, a3 = 0ull;
    const ull* spu = (const ull*)sp;
    #pragma unroll 8
    for (int c = 0; c < 256; c++) {
        float w = w1[(size_t)c * 256];
        ull w2;
        asm("mov.b64 %0, {%1, %1};" : "=l"(w2) : "r"(__float_as_uint(w)));
        asm("fma.rn.f32x2 %0, %1, %2, %0;" : "+l"(a0) : "l"(spu[c*4+0]), "l"(w2));
        asm("fma.rn.f32x2 %0, %1, %2, %0;" : "+l"(a1) : "l"(spu[c*4+1]), "l"(w2));
        asm("fma.rn.f32x2 %0, %1, %2, %0;" : "+l"(a2) : "l"(spu[c*4+2]), "l"(w2));
        asm("fma.rn.f32x2 %0, %1, %2, %0;" : "+l"(a3) : "l"(spu[c*4+3]), "l"(w2));
    }

    float af[8];
    {
        unsigned lo, hi;
        asm("mov.b64 {%0, %1}, %2;" : "=r"(lo), "=r"(hi) : "l"(a0));
        af[0] = __uint_as_float(lo); af[1] = __uint_as_float(hi);
        asm("mov.b64 {%0, %1}, %2;" : "=r"(lo), "=r"(hi) : "l"(a1));
        af[2] = __uint_as_float(lo); af[3] = __uint_as_float(hi);
        asm("mov.b64 {%0, %1}, %2;" : "=r"(lo), "=r"(hi) : "l"(a2));
        af[4] = __uint_as_float(lo); af[5] = __uint_as_float(hi);
        asm("mov.b64 {%0, %1}, %2;" : "=r"(lo), "=r"(hi) : "l"(a3));
        af[6] = __uint_as_float(lo); af[7] = __uint_as_float(hi);
    }

    float* pp = g_part + (size_t)kc * (KSEL*FEAT) + (size_t)(g * 8) * 256 + tid;
    #pragma unroll
    for (int r = 0; r < 8; r++) pp[(size_t)r * 256] = af[r];
}

// ------- tail: reduce partials + BN/ReLU + GEMM2 + masked out. 2 rois/block -
__global__ void __launch_bounds__(128) k_tail(const float* __restrict__ b1,
                                              const float* __restrict__ gamma,
                                              const float* __restrict__ beta,
                                              const float* __restrict__ mm,
                                              const float* __restrict__ mv,
                                              const float* __restrict__ W2,
                                              const float* __restrict__ b2,
                                              float* __restrict__ out) {
    __shared__ float sh[2*FEAT];
    __shared__ float srois[8];
    int r0  = blockIdx.x * 2;
    int tid = threadIdx.x;
    if (tid < 8) srois[tid] = g_rois[r0*4 + tid];

    #pragma unroll
    for (int q = 0; q < 4; q++) {
        int i = q*128 + tid;          // i < 512: roi = i>>8, col = i&255
        int roi = i >> 8, col = i & 255;
        const float* pp = g_part + (size_t)(r0 + roi) * 256 + col;
        float s = pp[0] + pp[KSEL*FEAT] + pp[2*KSEL*FEAT] + pp[3*KSEL*FEAT];
        float hv = (s + b1[col] - mm[col]) * rsqrtf(mv[col] + 1e-3f) * gamma[col] + beta[col];
        sh[i] = fmaxf(hv, 0.0f);
    }
    __syncthreads();

    // 2 rois x 84 outs = 168 dots over 256
    #pragma unroll
    for (int q = 0; q < 2; q++) {
        int j = q*128 + tid;
        if (j < 168) {
            int r = (j >= 84) ? 1 : 0;
            int o = j - r*84;
            int kg = r0 + r;
            float acc = b2[o];
            const float* hrow = &sh[r*FEAT];
            #pragma unroll 4
            for (int c = 0; c < 256; c++) acc += hrow[c] * W2[c*OUTC + o];
            float keepf = (float)g_keep[kg];
            if (o < 4) out[KSEL*80 + kg*4 + o] = (srois[r*4 + o] + acc) * keepf;
            else       out[(size_t)kg*80 + (o - 4)] = acc * keepf;
        } else if (j < 170) {
            int kg = r0 + (j - 168);
            out[KSEL*80 + KSEL*4 + kg] = (float)g_keep[kg];
        }
    }
}

// ---------------- launch ----------------------------------------------------
extern "C" void kernel_launch(void* const* d_in, const int* in_sizes, int n_in,
                              void* d_out, int out_size) {
    const float* pred    = (const float*)d_in[0];
    const float* rois    = (const float*)d_in[1];
    const float* anchors = (const float*)d_in[2];
    const int*   assign  = (const int*)  d_in[3];
    const float* feats   = (const float*)d_in[4];
    const float* W1      = (const float*)d_in[5];
    const float* b1      = (const float*)d_in[6];
    const float* gamma   = (const float*)d_in[7];
    const float* beta    = (const float*)d_in[8];
    const float* mm      = (const float*)d_in[9];
    const float* mv      = (const float*)d_in[10];
    const float* W2      = (const float*)d_in[11];
    const float* b2      = (const float*)d_in[12];
    float* out = (float*)d_out;

    k_filter<<<(NTOT + 255) / 256, 256>>>(pred);
    k_select<<<1, 1024>>>(rois, anchors, assign);
    k_supres<<<16, 512>>>();
    k_roialign<<<KSEL, 256>>>(feats);
    k_gemm1a<<<dim3(64, 4), 256>>>(W1);
    k_tail<<<KSEL / 2, 128>>>(b1, gamma, beta, mm, mv, W2, b2, out);
}

// round 6
// speedup vs baseline: 1.7502x; 1.0773x over previous
#include <cuda_runtime.h>
#include <stdint.h>

#define NTOT  (8*32*32*9)   // 73728
#define KSEL  512
#define HF_   32
#define WF_   32
#define CCH   1024
#define FEAT  256
#define OUTC  84
#define SS_   14
#define NSAMP 196
#define DET_THRC 0.7f
#define NMS_IOUC 0.7f
#define NBINS 4096
#define NKC   8                 // K chunks in gemm1
#define GRP   16                // rois per gemm1 group

typedef unsigned long long ull;

// ---------------- device scratch (static globals; zero-initialized) ---------
__device__ uint64_t g_cand[NTOT];
__device__ int      g_cand_count;                 // reset by k_select
__device__ __align__(16) int g_hist[NBINS];       // reset by k_select
__device__ int      g_valid[KSEL];
__device__ int      g_assign[KSEL];
__device__ float    g_rois[KSEL*4];
__device__ float    g_shifted[KSEL*4];
__device__ unsigned g_sup[KSEL*16];
__device__ unsigned g_supany[16];                 // reset by resolver
__device__ int      g_keep[KSEL];
__device__ int      g_done;                       // reset by resolver
__device__ int      g_cnt[KSEL];
__device__ int      g_plist[KSEL*128];
__device__ float    g_wlist[KSEL*128];
__device__ __align__(16) float g_poolT[KSEL*CCH];       // [grp=k/16][c][k%16]
__device__ __align__(16) float g_part[NKC*KSEL*FEAT];   // [kc][roi][col]

// ---------------- filter: score > 0.7 -> key + 4096-bin histogram -----------
__global__ void k_filter(const float* __restrict__ pred) {
    int i = blockIdx.x * blockDim.x + threadIdx.x;
    float s = (i < NTOT) ? pred[i] : 0.0f;
    bool c = (s > DET_THRC);
    unsigned m = __ballot_sync(0xffffffffu, c);
    int n = __popc(m);
    int base = 0;
    if ((threadIdx.x & 31) == 0 && n)
        base = atomicAdd(&g_cand_count, n);
    base = __shfl_sync(0xffffffffu, base, 0);
    if (c) {
        int r = __popc(m & ((1u << (threadIdx.x & 31)) - 1u));
        unsigned u = __float_as_uint(s); // s > 0 -> monotone as unsigned
        g_cand[base + r] = ((uint64_t)u << 32) | (unsigned)(0xFFFFFFFFu - (unsigned)i);
        atomicAdd(&g_hist[u >> 19], 1);
    }
}

// ------- single-block: histogram cutoff + 1-pass collect + hybrid bitonic ---
__global__ void __launch_bounds__(1024) k_select(const float* __restrict__ rois,
                                                 const float* __restrict__ anchors,
                                                 const int*   __restrict__ assign) {
    __shared__ int      sh_hist[NBINS];
    __shared__ int      sh_chunk[1024];
    __shared__ int      sh_warp[32];
    __shared__ unsigned sh_T;
    __shared__ int      sh_cnt;
    __shared__ uint64_t sh_keys[1024];
    int tid = threadIdx.x;
    int lane = tid & 31, wid = tid >> 5;

    int M = g_cand_count; if (M > NTOT) M = NTOT;
    __syncthreads();
    if (tid == 0) { g_cand_count = 0; sh_cnt = 0; }

    int4 h = ((const int4*)g_hist)[tid];
    ((int4*)g_hist)[tid] = make_int4(0, 0, 0, 0);
    sh_hist[tid*4+0] = h.x; sh_hist[tid*4+1] = h.y;
    sh_hist[tid*4+2] = h.z; sh_hist[tid*4+3] = h.w;
    int csum = h.x + h.y + h.z + h.w;
    sh_chunk[tid] = csum;
    int ws = csum;
    #pragma unroll
    for (int off = 16; off > 0; off >>= 1) ws += __shfl_down_sync(0xffffffffu, ws, off);
    if (lane == 0) sh_warp[wid] = ws;
    __syncthreads();

    if (tid == 0) {
        unsigned T = 1u;
        int cum = 0; int w;
        bool found = false;
        for (w = 31; w >= 0; w--) {
            if (cum + sh_warp[w] >= KSEL) { found = true; break; }
            cum += sh_warp[w];
        }
        if (found) {
            int c;
            for (c = 31; c >= 0; c--) {
                int t = sh_chunk[w*32 + c];
                if (cum + t >= KSEL) break;
                cum += t;
            }
            int base = (w*32 + c) * 4;
            int b;
            for (b = 3; b >= 0; b--) {
                int t = sh_hist[base + b];
                if (cum + t >= KSEL) break;
                cum += t;
            }
            T = (unsigned)(base + b) << 19;
        }
        sh_T = T;
    }
    __syncthreads();
    unsigned T = sh_T;

    for (int j = tid; j < M; j += 1024) {
        uint64_t k = g_cand[j];
        if ((unsigned)(k >> 32) >= T) {
            int p = atomicAdd(&sh_cnt, 1);
            if (p < 1024) sh_keys[p] = k;
        }
    }
    __syncthreads();
    int cnt = sh_cnt; if (cnt > 1024) cnt = 1024;
    if (tid >= cnt) sh_keys[tid] = 0ull;
    __syncthreads();

    // hybrid bitonic sort (descending)
    uint64_t v = sh_keys[tid];
    #pragma unroll
    for (int size = 2; size <= 32; size <<= 1) {
        #pragma unroll
        for (int stride = size >> 1; stride >= 1; stride >>= 1) {
            uint64_t o = __shfl_xor_sync(0xffffffffu, v, stride);
            bool lower = (tid & stride) == 0;
            bool desc  = (tid & size) == 0;
            uint64_t mx = v > o ? v : o, mn = v > o ? o : v;
            v = (desc == lower) ? mx : mn;
        }
    }
    sh_keys[tid] = v;
    __syncthreads();
    for (int size = 64; size <= 1024; size <<= 1) {
        for (int stride = size >> 1; stride >= 32; stride >>= 1) {
            int j = tid ^ stride;
            if (j > tid) {
                uint64_t a = sh_keys[tid], b = sh_keys[j];
                bool desc = (tid & size) == 0;
                if (desc ? (a < b) : (a > b)) { sh_keys[tid] = b; sh_keys[j] = a; }
            }
            __syncthreads();
        }
        v = sh_keys[tid];
        #pragma unroll
        for (int stride = 16; stride >= 1; stride >>= 1) {
            uint64_t o = __shfl_xor_sync(0xffffffffu, v, stride);
            bool lower = (tid & stride) == 0;
            bool desc  = (tid & size) == 0;
            uint64_t mx = v > o ? v : o, mn = v > o ? o : v;
            v = (desc == lower) ? mx : mn;
        }
        sh_keys[tid] = v;
        __syncthreads();
    }

    if (tid < KSEL) {
        uint64_t k = sh_keys[tid];
        unsigned u = (unsigned)(k >> 32);
        int idx = 0, vv = 0;
        if (u != 0u) { idx = (int)(0xFFFFFFFFu - (unsigned)(k & 0xFFFFFFFFu)); vv = 1; }
        g_valid[tid] = vv;
        int a = assign[idx];
        g_assign[tid] = a;
        float fa = (float)a * 1024.0f;
        #pragma unroll
        for (int c = 0; c < 4; c++) g_rois[tid*4 + c] = rois[idx*4 + c];
        float cy = anchors[idx*4+0], cx = anchors[idx*4+1];
        float hh = anchors[idx*4+2], ww = anchors[idx*4+3];
        g_shifted[tid*4+0] = cy - hh*0.5f + fa;
        g_shifted[tid*4+1] = cx - ww*0.5f + fa;
        g_shifted[tid*4+2] = cy + hh*0.5f + fa;
        g_shifted[tid*4+3] = cx + ww*0.5f + fa;
    }
}

// --- 512 blocks: roi weight-list prep + per-roi NMS sup; last block resolves
__global__ void __launch_bounds__(256) k_supres() {
    __shared__ float4   sb[KSEL];
    __shared__ float    wmap[1024];
    __shared__ int      plist[128];
    __shared__ float    wlist[128];
    __shared__ int      cnt;
    __shared__ int      s_last;
    int k   = blockIdx.x;
    int tid = threadIdx.x;

    const float4* gs = (const float4*)g_shifted;
    #pragma unroll
    for (int i = tid; i < KSEL; i += 256) sb[i] = gs[i];
    for (int i = tid; i < 1024; i += 256) wmap[i] = 0.0f;
    if (tid == 0) cnt = 0;
    __syncthreads();

    // --- sup words for roi k (threads 0..15) ---
    if (tid < 16) {
        float4 bi = sb[k];
        float ai = (bi.z - bi.x) * (bi.w - bi.y);
        unsigned bits = 0u;
        #pragma unroll 8
        for (int b = 0; b < 32; b++) {
            int j = tid*32 + b;
            if (j > k) {
                float4 bj = sb[j];
                float yA = fmaxf(bi.x, bj.x), xA = fmaxf(bi.y, bj.y);
                float yB = fminf(bi.z, bj.z), xB = fminf(bi.w, bj.w);
                float inter = fmaxf(yB - yA, 0.0f) * fmaxf(xB - xA, 0.0f);
                float aj = (bj.z - bj.x) * (bj.w - bj.y);
                if (inter > NMS_IOUC * (ai + aj - inter + 1e-8f)) bits |= (1u << b);
            }
        }
        g_sup[k*16 + tid] = bits;
        if (bits) atomicOr(&g_supany[k >> 5], 1u << (k & 31));
    }

    // --- weight-list prep for roi k ---
    if (tid < NSAMP) {
        const float sc = 32.0f / 1024.0f;
        float ry1 = g_rois[k*4+0] * sc, rx1 = g_rois[k*4+1] * sc;
        float ry2 = g_rois[k*4+2] * sc, rx2 = g_rois[k*4+3] * sc;
        int sy = tid / SS_, sx = tid % SS_;
        float fy = ((float)sy + 0.5f) / (float)SS_;
        float fx = ((float)sx + 0.5f) / (float)SS_;
        float yy = ry1 + fy * (ry2 - ry1) - 0.5f;
        float xx = rx1 + fx * (rx2 - rx1) - 0.5f;
        float yc = fminf(fmaxf(yy, 0.0f), 31.0f);
        float xc = fminf(fmaxf(xx, 0.0f), 31.0f);
        float y0 = floorf(yc), x0 = floorf(xc);
        float wy = yc - y0,  wx = xc - x0;
        int y0i = (int)y0, x0i = (int)x0;
        int y1i = min(y0i + 1, 31), x1i = min(x0i + 1, 31);
        atomicAdd(&wmap[y0i*32 + x0i], (1.0f - wy) * (1.0f - wx));
        atomicAdd(&wmap[y0i*32 + x1i], (1.0f - wy) * wx);
        atomicAdd(&wmap[y1i*32 + x0i], wy * (1.0f - wx));
        atomicAdd(&wmap[y1i*32 + x1i], wy * wx);
    }
    __syncthreads();
    for (int p = tid; p < 1024; p += 256) {
        float w = wmap[p];
        if (w != 0.0f) {
            int pos = atomicAdd(&cnt, 1);
            plist[pos] = p; wlist[pos] = w;
        }
    }
    __syncthreads();
    int n = cnt;
    if (tid == 0) g_cnt[k] = n;
    if (tid < n) { g_plist[k*128 + tid] = plist[tid]; g_wlist[k*128 + tid] = wlist[tid]; }

    // --- grid arrival: last block does the greedy resolve ---
    __threadfence();
    __syncthreads();
    if (tid == 0) s_last = (atomicAdd(&g_done, 1) == KSEL - 1) ? 1 : 0;
    __syncthreads();
    if (!s_last) return;

    __shared__ unsigned ssup[KSEL*16];
    __shared__ unsigned sany[16];
    __shared__ unsigned sword[16];
    __threadfence();
    #pragma unroll
    for (int i = tid; i < KSEL*16; i += 256) ssup[i] = g_sup[i];
    #pragma unroll
    for (int q = 0; q < 2; q++) {
        int i = q*256 + tid;
        int v = g_valid[i];
        unsigned bm = __ballot_sync(0xffffffffu, v != 0);
        if ((i & 31) == 0) sword[i >> 5] = bm;
    }
    if (tid < 16) { sany[tid] = g_supany[tid]; g_supany[tid] = 0u; }
    if (tid == 0) g_done = 0;
    __syncthreads();

    if (tid < 32) {
        int lane = tid;
        unsigned word = (lane < 16) ? sword[lane] : 0u;
        for (int ww = 0; ww < 16; ww++) {
            unsigned anyw = sany[ww];
            if (!anyw) continue;
            for (int b = 0; b < 32; b++) {
                if (!((anyw >> b) & 1u)) continue;
                int ii = ww*32 + b;
                unsigned wi = __shfl_sync(0xffffffffu, word, ww);
                if ((wi >> b) & 1u) {
                    if (lane < 16) word &= ~ssup[ii*16 + lane];
                }
            }
        }
        if (lane < 16) sword[lane] = word;
    }
    __syncthreads();
    #pragma unroll
    for (int q = 0; q < 2; q++) {
        int i = q*256 + tid;
        g_keep[i] = (int)((sword[i >> 5] >> (i & 31)) & 1u);
    }
}

// ------- gather: (roi, channel-half) = 1024 blocks x 128 thr, streaming -----
__global__ void __launch_bounds__(128) k_gather(const float* __restrict__ feats) {
    __shared__ int   spl[128];
    __shared__ float swl[128];
    __shared__ int   scnt;
    __shared__ int   sas;
    int k   = blockIdx.x;
    int h   = blockIdx.y;
    int tid = threadIdx.x;
    if (tid == 0) { scnt = g_cnt[k]; sas = g_assign[k]; }
    spl[tid] = g_plist[k*128 + tid];
    swl[tid] = g_wlist[k*128 + tid];
    __syncthreads();

    int n = scnt;
    const float4* fb = (const float4*)(feats + (size_t)sas * (HF_*WF_*CCH)) + h*128 + tid;
    float ax = 0.f, ay = 0.f, az = 0.f, aw = 0.f;
    #pragma unroll 4
    for (int e = 0; e < n; e++) {
        int   p = spl[e];
        float w = swl[e];
        float4 vv = fb[(size_t)p * 256];
        ax += w * vv.x; ay += w * vv.y; az += w * vv.z; aw += w * vv.w;
    }
    const float inv = 1.0f / 196.0f;
    float* po = g_poolT + (size_t)(k >> 4) * (CCH*GRP) + (k & 15);
    int c0 = (h*128 + tid) * 4;
    po[(c0+0)*GRP] = ax * inv;
    po[(c0+1)*GRP] = ay * inv;
    po[(c0+2)*GRP] = az * inv;
    po[(c0+3)*GRP] = aw * inv;
}

// ------- GEMM1a: (32 groups of 16 rois, 8 K-chunks of 128) x 256 thr --------
__global__ void __launch_bounds__(256) k_gemm1a(const float* __restrict__ W1) {
    __shared__ __align__(16) float sp[128*GRP];   // [c in chunk][16 rois] 8KB
    int g   = blockIdx.x;
    int kc  = blockIdx.y;
    int tid = threadIdx.x;   // output col

    const float4* src = (const float4*)(g_poolT + (size_t)g * (CCH*GRP) + kc * (128*GRP));
    float4* dst = (float4*)sp;
    #pragma unroll
    for (int i = tid; i < 128*GRP/4; i += 256) dst[i] = src[i];
    __syncthreads();

    const float* w1 = W1 + (size_t)(kc * 128) * 256 + tid;
    ull a[8];
    #pragma unroll
    for (int j = 0; j < 8; j++) a[j] = 0ull;
    const ull* spu = (const ull*)sp;
    #pragma unroll 4
    for (int c = 0; c < 128; c++) {
        float w = w1[(size_t)c * 256];
        ull w2;
        asm("mov.b64 %0, {%1, %1};" : "=l"(w2) : "r"(__float_as_uint(w)));
        #pragma unroll
        for (int j = 0; j < 8; j++)
            asm("fma.rn.f32x2 %0, %1, %2, %0;" : "+l"(a[j]) : "l"(spu[c*8+j]), "l"(w2));
    }

    float* pp = g_part + (size_t)kc * (KSEL*FEAT) + (size_t)(g * GRP) * 256 + tid;
    #pragma unroll
    for (int j = 0; j < 8; j++) {
        unsigned lo, hi;
        asm("mov.b64 {%0, %1}, %2;" : "=r"(lo), "=r"(hi) : "l"(a[j]));
        pp[(size_t)(2*j  ) * 256] = __uint_as_float(lo);
        pp[(size_t)(2*j+1) * 256] = __uint_as_float(hi);
    }
}

// ------- tail: reduce 8 partials + BN/ReLU + GEMM2 + masked out -------------
__global__ void __launch_bounds__(128) k_tail(const float* __restrict__ b1,
                                              const float* __restrict__ gamma,
                                              const float* __restrict__ beta,
                                              const float* __restrict__ mm,
                                              const float* __restrict__ mv,
                                              const float* __restrict__ W2,
                                              const float* __restrict__ b2,
                                              float* __restrict__ out) {
    __shared__ float sh[2*FEAT];
    __shared__ float srois[8];
    int r0  = blockIdx.x * 2;
    int tid = threadIdx.x;
    if (tid < 8) srois[tid] = g_rois[r0*4 + tid];

    #pragma unroll
    for (int q = 0; q < 4; q++) {
        int i = q*128 + tid;          // i < 512: roi = i>>8, col = i&255
        int roi = i >> 8, col = i & 255;
        const float* pp = g_part + (size_t)(r0 + roi) * 256 + col;
        float s = 0.0f;
        #pragma unroll
        for (int kc = 0; kc < NKC; kc++) s += pp[(size_t)kc * (KSEL*FEAT)];
        float hv = (s + b1[col] - mm[col]) * rsqrtf(mv[col] + 1e-3f) * gamma[col] + beta[col];
        sh[i] = fmaxf(hv, 0.0f);
    }
    __syncthreads();

    #pragma unroll
    for (int q = 0; q < 2; q++) {
        int j = q*128 + tid;
        if (j < 168) {
            int r = (j >= 84) ? 1 : 0;
            int o = j - r*84;
            int kg = r0 + r;
            float acc = b2[o];
            const float* hrow = &sh[r*FEAT];
            #pragma unroll 4
            for (int c = 0; c < 256; c++) acc += hrow[c] * W2[c*OUTC + o];
            float keepf = (float)g_keep[kg];
            if (o < 4) out[KSEL*80 + kg*4 + o] = (srois[r*4 + o] + acc) * keepf;
            else       out[(size_t)kg*80 + (o - 4)] = acc * keepf;
        } else if (j < 170) {
            int kg = r0 + (j - 168);
            out[KSEL*80 + KSEL*4 + kg] = (float)g_keep[kg];
        }
    }
}

// ---------------- launch ----------------------------------------------------
extern "C" void kernel_launch(void* const* d_in, const int* in_sizes, int n_in,
                              void* d_out, int out_size) {
    const float* pred    = (const float*)d_in[0];
    const float* rois    = (const float*)d_in[1];
    const float* anchors = (const float*)d_in[2];
    const int*   assign  = (const int*)  d_in[3];
    const float* feats   = (const float*)d_in[4];
    const float* W1      = (const float*)d_in[5];
    const float* b1      = (const float*)d_in[6];
    const float* gamma   = (const float*)d_in[7];
    const float* beta    = (const float*)d_in[8];
    const float* mm      = (const float*)d_in[9];
    const float* mv      = (const float*)d_in[10];
    const float* W2      = (const float*)d_in[11];
    const float* b2      = (const float*)d_in[12];
    float* out = (float*)d_out;

    k_filter<<<(NTOT + 255) / 256, 256>>>(pred);
    k_select<<<1, 1024>>>(rois, anchors, assign);
    k_supres<<<KSEL, 256>>>();
    k_gather<<<dim3(KSEL, 2), 128>>>(feats);
    k_gemm1a<<<dim3(KSEL/GRP, NKC), 256>>>(W1);
    k_tail<<<KSEL / 2, 128>>>(b1, gamma, beta, mm, mv, W2, b2, out);
}